// round 4
// baseline (speedup 1.0000x reference)
#include <cuda_runtime.h>
#include <cstdint>

#define En 4096
#define Bn 8
#define HEADS 32
#define Dh 128
#define CK 128            // k-floats per pipeline chunk
#define NC (En / CK)      // 32 chunks
#define RB 8              // W rows per block
#define SN 5              // pipeline stages

typedef unsigned long long u64;

__device__ __align__(16) float g_qkv[3 * Bn * En];
__device__ __align__(16) float g_o[Bn * En];

__device__ __forceinline__ void fma2(u64 &d, u64 a, u64 b) {
    asm("fma.rn.f32x2 %0, %1, %2, %0;" : "+l"(d) : "l"(a), "l"(b));
}
__device__ __forceinline__ float2 unpack2(u64 v) {
    float2 r;
    asm("mov.b64 {%0,%1}, %2;" : "=f"(r.x), "=f"(r.y) : "l"(v));
    return r;
}
__device__ __forceinline__ void cp16(uint32_t saddr, const float* g) {
    asm volatile("cp.async.cg.shared.global [%0], [%1], 16;" :: "r"(saddr), "l"(g));
}

struct SmemTiles {
    float w[SN][RB][CK];  // 5 * 4KB
    float x[SN][Bn][CK];  // 5 * 4KB
};                        // 40KB total

// Block (128 thr, 4 warps) computes out[b][row0+r] for 8 rows x 8 batches,
// reducing over all 4096 k via a 5-stage cp.async pipeline.
__device__ __forceinline__ void gemm_block8(const float* __restrict__ W,
                                            const float* __restrict__ X,
                                            float* __restrict__ out,
                                            int row0) {
    __shared__ SmemTiles sm;
    const int t = threadIdx.x;
    const int warp = t >> 5, lane = t & 31;

    uint32_t sw_base = (uint32_t)__cvta_generic_to_shared(&sm.w[0][0][0]);
    uint32_t sx_base = (uint32_t)__cvta_generic_to_shared(&sm.x[0][0][0]);

    // stage: W = 256 x 16B units, x = 256 x 16B units, 128 threads
    auto issue_stage = [&](int st, int kc) {
        uint32_t sw = sw_base + st * (RB * CK * 4);
        uint32_t sx = sx_base + st * (Bn * CK * 4);
#pragma unroll
        for (int p = 0; p < 2; ++p) {
            int u = p * 128 + t;
            int r = u >> 5, c = u & 31;
            cp16(sw + u * 16, W + (size_t)(row0 + r) * En + kc * CK + c * 4);
        }
#pragma unroll
        for (int p = 0; p < 2; ++p) {
            int u = p * 128 + t;
            int b = u >> 5, c = u & 31;
            cp16(sx + u * 16, X + (size_t)b * En + kc * CK + c * 4);
        }
        asm volatile("cp.async.commit_group;");
    };

    // prologue: fill SN-1 stages
#pragma unroll
    for (int s = 0; s < SN - 1; ++s) issue_stage(s, s);

    u64 acc[16];  // [r(2)][b(8)] packed (even-k, odd-k)
#pragma unroll
    for (int i = 0; i < 16; ++i) acc[i] = 0ull;

    for (int i = 0; i < NC; ++i) {
        asm volatile("cp.async.wait_group %0;" :: "n"(SN - 2));
        __syncthreads();

        int nk = i + SN - 1;
        if (nk < NC) issue_stage(nk % SN, nk);
        else asm volatile("cp.async.commit_group;");

        int st = i % SN;
        longlong2 w0 = *reinterpret_cast<const longlong2*>(&sm.w[st][warp * 2 + 0][lane * 4]);
        longlong2 w1 = *reinterpret_cast<const longlong2*>(&sm.w[st][warp * 2 + 1][lane * 4]);
#pragma unroll
        for (int b = 0; b < 8; ++b) {
            longlong2 xv = *reinterpret_cast<const longlong2*>(&sm.x[st][b][lane * 4]);
            fma2(acc[0 + b], (u64)w0.x, (u64)xv.x);
            fma2(acc[8 + b], (u64)w1.x, (u64)xv.x);
            fma2(acc[0 + b], (u64)w0.y, (u64)xv.y);
            fma2(acc[8 + b], (u64)w1.y, (u64)xv.y);
        }
    }

    // collapse packed halves -> 16 scalars per thread
    float vals[16];
#pragma unroll
    for (int i = 0; i < 16; ++i) {
        float2 p = unpack2(acc[i]);
        vals[i] = p.x + p.y;
    }

    // butterfly transpose-reduce (16 values across 32 lanes)
    int n = 16;
#pragma unroll
    for (int m = 1; m <= 8; m <<= 1) {
        n >>= 1;
        bool up = (lane & m) != 0;
#pragma unroll
        for (int i = 0; i < n; ++i) {
            float keep = up ? vals[i + n] : vals[i];
            float send = up ? vals[i] : vals[i + n];
            keep += __shfl_xor_sync(0xffffffffu, send, m);
            vals[i] = keep;
        }
    }
    vals[0] += __shfl_xor_sync(0xffffffffu, vals[0], 16);

    if (lane < 16) {
        int j = ((lane & 1) << 3) | ((lane & 2) << 1) | ((lane >> 1) & 2) | ((lane >> 3) & 1);
        int r = j >> 3;
        int b = j & 7;
        out[(size_t)b * En + row0 + warp * 2 + r] = vals[0];
    }
}

// grid (512, 3), block 128
__global__ void __launch_bounds__(128, 5)
qkv_kernel(const float* __restrict__ Wq, const float* __restrict__ Wk,
           const float* __restrict__ Wv, const float* __restrict__ x) {
    const float* W = (blockIdx.y == 0) ? Wq : ((blockIdx.y == 1) ? Wk : Wv);
    gemm_block8(W, x, g_qkv + blockIdx.y * (Bn * En), blockIdx.x * RB);
}

// Attention with all-ones KV cache collapses to o[d] = c1 + c2 * v[d] per (b,h).
__global__ void __launch_bounds__(256)
attn_kernel() {
    int gtid = blockIdx.x * blockDim.x + threadIdx.x;
    int warp = gtid >> 5;   // 0..255
    int lane = gtid & 31;
    int b = warp >> 5;      // 0..7
    int h = warp & 31;      // 0..31

    const float4* q4 = reinterpret_cast<const float4*>(g_qkv + (0 * Bn + b) * En + h * Dh);
    const float4* k4 = reinterpret_cast<const float4*>(g_qkv + (1 * Bn + b) * En + h * Dh);
    const float4* v4 = reinterpret_cast<const float4*>(g_qkv + (2 * Bn + b) * En + h * Dh);

    float4 qv = q4[lane];
    float4 kv = k4[lane];
    float4 vv = v4[lane];

    float sq = qv.x + qv.y + qv.z + qv.w;
    float dp = qv.x * kv.x + qv.y * kv.y + qv.z * kv.z + qv.w * kv.w;
#pragma unroll
    for (int m = 16; m >= 1; m >>= 1) {
        sq += __shfl_xor_sync(0xffffffffu, sq, m);
        dp += __shfl_xor_sync(0xffffffffu, dp, m);
    }

    const float scale = 0.08838834764831845f;  // 1/sqrt(128)
    float s0 = sq * scale;                      // score vs every all-ones cache row
    float sL = dp * scale;                      // score vs appended k
    float mx = fmaxf(s0, sL);
    float e0 = expf(s0 - mx);
    float eL = expf(sL - mx);
    float inv = 1.0f / (4095.0f * e0 + eL);
    float c1 = 4095.0f * e0 * inv;              // total weight on ones-rows
    float c2 = eL * inv;                        // weight on appended v

    float4* o4 = reinterpret_cast<float4*>(g_o + b * En + h * Dh);
    o4[lane] = make_float4(c1 + c2 * vv.x, c1 + c2 * vv.y,
                           c1 + c2 * vv.z, c1 + c2 * vv.w);
}

// grid 512, block 128
__global__ void __launch_bounds__(128, 5)
oproj_kernel(const float* __restrict__ Wo, float* __restrict__ out) {
    gemm_block8(Wo, g_o, out, blockIdx.x * RB);
}

extern "C" void kernel_launch(void* const* d_in, const int* in_sizes, int n_in,
                              void* d_out, int out_size) {
    const float* x  = (const float*)d_in[0];
    const float* Wq = (const float*)d_in[1];
    const float* Wk = (const float*)d_in[2];
    const float* Wv = (const float*)d_in[3];
    const float* Wo = (const float*)d_in[4];
    float* out = (float*)d_out;

    dim3 gq(512, 3);
    qkv_kernel<<<gq, 128>>>(Wq, Wk, Wv, x);
    attn_kernel<<<32, 256>>>();
    oproj_kernel<<<512, 128>>>(Wo, out);
}

// round 5
// speedup vs baseline: 1.1775x; 1.1775x over previous
#include <cuda_runtime.h>
#include <cstdint>

#define En 4096
#define Bn 8
#define HEADS 32
#define Dh 128
#define CK 128              // k-floats per chunk
#define RB 16               // W rows per block
#define SN 4                // pipeline stages
#define KS 2                // k-splits per output row
#define KCH (En / (CK * KS))// 16 chunks per block

typedef unsigned long long u64;

__device__ __align__(16) float g_qkv[3 * Bn * En];
__device__ __align__(16) float g_o[Bn * En];

__device__ __forceinline__ void fma2(u64 &d, u64 a, u64 b) {
    asm("fma.rn.f32x2 %0, %1, %2, %0;" : "+l"(d) : "l"(a), "l"(b));
}
__device__ __forceinline__ float2 unpack2(u64 v) {
    float2 r;
    asm("mov.b64 {%0,%1}, %2;" : "=f"(r.x), "=f"(r.y) : "l"(v));
    return r;
}
__device__ __forceinline__ void cp16(uint32_t saddr, const float* g) {
    asm volatile("cp.async.cg.shared.global [%0], [%1], 16;" :: "r"(saddr), "l"(g));
}

struct SmemTiles {
    float w[SN][RB][CK];  // 4 x 8KB
    float x[SN][Bn][CK];  // 4 x 4KB
};                        // 48KB

// Block (128 thr, 4 warps): 16 rows x 8 batches over k-range [k0, k0+2048),
// partial sums atomicAdd'ed into out (zero-initialized upfront).
__device__ __forceinline__ void gemm_block(const float* __restrict__ W,
                                           const float* __restrict__ X,
                                           float* __restrict__ out,
                                           int row0, int k0) {
    __shared__ SmemTiles sm;
    const int t = threadIdx.x;
    const int warp = t >> 5, lane = t & 31;

    uint32_t swb = (uint32_t)__cvta_generic_to_shared(&sm.w[0][0][0]);
    uint32_t sxb = (uint32_t)__cvta_generic_to_shared(&sm.x[0][0][0]);

    // Hoisted per-thread copy descriptors (4 W units + 2 x units of 16B)
    const float* wg[4]; uint32_t wsm[4];
#pragma unroll
    for (int p = 0; p < 4; ++p) {
        int u = p * 128 + t, r = u >> 5, c = u & 31;
        wg[p] = W + (size_t)(row0 + r) * En + k0 + c * 4;
        wsm[p] = swb + u * 16;
    }
    const float* xg[2]; uint32_t xsm[2];
#pragma unroll
    for (int p = 0; p < 2; ++p) {
        int u = p * 128 + t, b = u >> 5, c = u & 31;
        xg[p] = X + (size_t)b * En + k0 + c * 4;
        xsm[p] = sxb + u * 16;
    }

    auto issue_stage = [&](int st, int kc) {
        int koff = kc * CK;
        uint32_t wo = st * (RB * CK * 4);
        uint32_t xo = st * (Bn * CK * 4);
#pragma unroll
        for (int p = 0; p < 4; ++p) cp16(wsm[p] + wo, wg[p] + koff);
#pragma unroll
        for (int p = 0; p < 2; ++p) cp16(xsm[p] + xo, xg[p] + koff);
        asm volatile("cp.async.commit_group;");
    };

#pragma unroll
    for (int s = 0; s < SN - 1; ++s) issue_stage(s, s);

    u64 acc[32];  // [r(4)][b(8)] packed (even-k, odd-k)
#pragma unroll
    for (int i = 0; i < 32; ++i) acc[i] = 0ull;

    for (int i = 0; i < KCH; ++i) {
        asm volatile("cp.async.wait_group %0;" :: "n"(SN - 2));
        __syncthreads();

        int nk = i + SN - 1;
        if (nk < KCH) issue_stage(nk % SN, nk);
        else asm volatile("cp.async.commit_group;");

        int st = i % SN;
        longlong2 wv[4];
#pragma unroll
        for (int r = 0; r < 4; ++r)
            wv[r] = *reinterpret_cast<const longlong2*>(&sm.w[st][warp * 4 + r][lane * 4]);
#pragma unroll
        for (int b = 0; b < 8; ++b) {
            longlong2 xv = *reinterpret_cast<const longlong2*>(&sm.x[st][b][lane * 4]);
#pragma unroll
            for (int r = 0; r < 4; ++r) {
                fma2(acc[r * 8 + b], (u64)wv[r].x, (u64)xv.x);
                fma2(acc[r * 8 + b], (u64)wv[r].y, (u64)xv.y);
            }
        }
    }

    float vals[32];
#pragma unroll
    for (int i = 0; i < 32; ++i) {
        float2 p = unpack2(acc[i]);
        vals[i] = p.x + p.y;
    }

    // butterfly transpose-reduce: lane L ends with value index bitrev5(L)
    int n = 32;
#pragma unroll
    for (int m = 1; m <= 16; m <<= 1) {
        n >>= 1;
        bool up = (lane & m) != 0;
#pragma unroll
        for (int i = 0; i < n; ++i) {
            float keep = up ? vals[i + n] : vals[i];
            float send = up ? vals[i] : vals[i + n];
            keep += __shfl_xor_sync(0xffffffffu, send, m);
            vals[i] = keep;
        }
    }
    int j = ((lane & 1) << 4) | ((lane & 2) << 2) | (lane & 4) |
            ((lane >> 2) & 2) | ((lane >> 4) & 1);
    int r = j >> 3;
    int b = j & 7;
    atomicAdd(&out[(size_t)b * En + row0 + warp * 4 + r], vals[0]);
}

// zero g_qkv (98304 f) and d_out (32768 f): 32768 float4 total
__global__ void __launch_bounds__(256)
init_kernel(float* __restrict__ out) {
    int i = blockIdx.x * 256 + threadIdx.x;  // 8192 threads
    float4 z = make_float4(0.f, 0.f, 0.f, 0.f);
    float4* q4 = reinterpret_cast<float4*>(g_qkv);
#pragma unroll
    for (int p = 0; p < 3; ++p) q4[p * 8192 + i] = z;
    reinterpret_cast<float4*>(out)[i] = z;
}

// grid (512, 3): blockIdx.x = rowblock*2 + ksplit; blockIdx.y = projection
__global__ void __launch_bounds__(128, 4)
qkv_kernel(const float* __restrict__ Wq, const float* __restrict__ Wk,
           const float* __restrict__ Wv, const float* __restrict__ x) {
    int rb = blockIdx.x >> 1, ks = blockIdx.x & 1;
    const float* W = (blockIdx.y == 0) ? Wq : ((blockIdx.y == 1) ? Wk : Wv);
    gemm_block(W, x, g_qkv + blockIdx.y * (Bn * En), rb * RB, ks * (En / KS));
}

// Attention with all-ones KV cache collapses to o[d] = c1 + c2 * v[d] per (b,h).
__global__ void __launch_bounds__(256)
attn_kernel() {
    int gtid = blockIdx.x * blockDim.x + threadIdx.x;
    int warp = gtid >> 5;
    int lane = gtid & 31;
    int b = warp >> 5;
    int h = warp & 31;

    const float4* q4 = reinterpret_cast<const float4*>(g_qkv + (0 * Bn + b) * En + h * Dh);
    const float4* k4 = reinterpret_cast<const float4*>(g_qkv + (1 * Bn + b) * En + h * Dh);
    const float4* v4 = reinterpret_cast<const float4*>(g_qkv + (2 * Bn + b) * En + h * Dh);

    float4 qv = q4[lane];
    float4 kv = k4[lane];
    float4 vv = v4[lane];

    float sq = qv.x + qv.y + qv.z + qv.w;
    float dp = qv.x * kv.x + qv.y * kv.y + qv.z * kv.z + qv.w * kv.w;
#pragma unroll
    for (int m = 16; m >= 1; m >>= 1) {
        sq += __shfl_xor_sync(0xffffffffu, sq, m);
        dp += __shfl_xor_sync(0xffffffffu, dp, m);
    }

    const float scale = 0.08838834764831845f;  // 1/sqrt(128)
    float s0 = sq * scale;
    float sL = dp * scale;
    float mx = fmaxf(s0, sL);
    float e0 = expf(s0 - mx);
    float eL = expf(sL - mx);
    float inv = 1.0f / (4095.0f * e0 + eL);
    float c1 = 4095.0f * e0 * inv;
    float c2 = eL * inv;

    float4* o4 = reinterpret_cast<float4*>(g_o + b * En + h * Dh);
    o4[lane] = make_float4(c1 + c2 * vv.x, c1 + c2 * vv.y,
                           c1 + c2 * vv.z, c1 + c2 * vv.w);
}

// grid 512: blockIdx.x = rowblock*2 + ksplit
__global__ void __launch_bounds__(128, 4)
oproj_kernel(const float* __restrict__ Wo, float* __restrict__ out) {
    int rb = blockIdx.x >> 1, ks = blockIdx.x & 1;
    gemm_block(Wo, g_o, out, rb * RB, ks * (En / KS));
}

extern "C" void kernel_launch(void* const* d_in, const int* in_sizes, int n_in,
                              void* d_out, int out_size) {
    const float* x  = (const float*)d_in[0];
    const float* Wq = (const float*)d_in[1];
    const float* Wk = (const float*)d_in[2];
    const float* Wv = (const float*)d_in[3];
    const float* Wo = (const float*)d_in[4];
    float* out = (float*)d_out;

    init_kernel<<<32, 256>>>(out);
    dim3 gq(512, 3);
    qkv_kernel<<<gq, 128>>>(Wq, Wk, Wv, x);
    attn_kernel<<<32, 256>>>();
    oproj_kernel<<<512, 128>>>(Wo, out);
}